// round 5
// baseline (speedup 1.0000x reference)
#include <cuda_runtime.h>
#include <cuda_bf16.h>
#include <cstdint>

#define N_NODES 50000
#define E_EDGES 800000
#define NB_STATS 240

// ---------------- device scratch (static, no allocs) ----------------
__device__ __align__(16) float  d_P[(size_t)N_NODES * 256];   // [fd|sd|fs|ss] per node
__device__ __align__(16) float  d_y0[(size_t)N_NODES * 64];
__device__ __align__(16) float  d_x1[(size_t)N_NODES * 64];
__device__ __align__(16) float  d_y1[(size_t)N_NODES * 64];
__device__ int    d_src[E_EDGES];
__device__ int    d_dst[E_EDGES];
__device__ int    d_deg[N_NODES];
__device__ int    d_fill[N_NODES];
__device__ int    d_rowptr[N_NODES + 1];
__device__ int    d_esrc[E_EDGES];
__device__ __align__(16) float  d_ea_s[(size_t)E_EDGES * 16]; // edge_attr permuted to CSR order
__device__ __align__(16) float  d_Wnode[2][64 * 256];         // [k][a*64+j]
__device__ __align__(16) float  d_Wq[2][16 * 128];            // [k][j], j<64 f, else s
__device__ float  d_bias2[2][256];
__device__ double d_psum[NB_STATS * 64];                      // per-block BN partials
__device__ double d_psq[NB_STATS * 64];
__device__ __align__(16) float  d_scale[2][64];
__device__ __align__(16) float  d_shift[2][64];
__device__ int    d_bound[65];                                // graph row boundaries
__device__ int    d_ei64;                                     // 1 if edge_index is int64-layout
__device__ int    d_b64;                                      // 1 if batch is int64-layout

__device__ __forceinline__ float sigmoid_f(float x) {
    return __fdividef(1.f, 1.f + __expf(-x));
}
__device__ __forceinline__ float softplus_f(float x) {
    return (x > 20.f) ? x : __logf(1.f + __expf(x));
}

// ---------------- dtype detection: int64 vs int32 index buffers ----------------
// If int64-layout, the high word of each value is 0. Probe reads are in-bounds
// under BOTH interpretations.
__global__ void detect_kernel(const int* __restrict__ ei32, const int* __restrict__ b32) {
    if (threadIdx.x == 0 && blockIdx.x == 0) {
        int o = 0;
        #pragma unroll
        for (int i = 1; i < 64; i += 2) o |= ei32[i];   // high halves if int64
        d_ei64 = (o == 0) ? 1 : 0;
        // batch sorted 0..63; word N-1 (odd) is a high half (0) iff int64
        d_b64 = (b32[N_NODES - 1] == 0) ? 1 : 0;
    }
}

// ---------------- prep: decode+clamp indices, pack weights, zero counters ----------------
__global__ void prep_kernel(const void* __restrict__ ei_raw,
                            const float* __restrict__ Wf0, const float* __restrict__ Ws0,
                            const float* __restrict__ bf0, const float* __restrict__ bs0,
                            const float* __restrict__ Wf1, const float* __restrict__ Ws1,
                            const float* __restrict__ bf1, const float* __restrict__ bs1) {
    int stride = gridDim.x * blockDim.x;
    int gid = blockIdx.x * blockDim.x + threadIdx.x;
    const int ei64 = d_ei64;
    const long long* eL = (const long long*)ei_raw;
    const int*       eI = (const int*)ei_raw;
    for (int i = gid; i < E_EDGES; i += stride) {
        int s, d;
        if (ei64) {
            s = (int)eL[i];
            d = (int)eL[E_EDGES + i];
        } else {
            s = eI[i];
            d = eI[E_EDGES + i];
        }
        s = min(max(s, 0), N_NODES - 1);
        d = min(max(d, 0), N_NODES - 1);
        d_src[i] = s;
        d_dst[i] = d;
    }
    for (int i = gid; i < N_NODES; i += stride) { d_deg[i] = 0; d_fill[i] = 0; }
    for (int i = gid; i < 2 * 64 * 144; i += stride) {
        int l = i / 9216; int r = i % 9216; int j = r / 144; int k = r % 144;
        const float* Wf = l ? Wf1 : Wf0;
        const float* Ws = l ? Ws1 : Ws0;
        float wf = Wf[j * 144 + k], ws = Ws[j * 144 + k];
        if (k < 64) {
            d_Wnode[l][k * 256 + j]       = wf;   // fd
            d_Wnode[l][k * 256 + 64 + j]  = ws;   // sd
        } else if (k < 128) {
            int kk = k - 64;
            d_Wnode[l][kk * 256 + 128 + j] = wf;  // fs
            d_Wnode[l][kk * 256 + 192 + j] = ws;  // ss
        } else {
            int kk = k - 128;
            d_Wq[l][kk * 128 + j]       = wf;
            d_Wq[l][kk * 128 + 64 + j]  = ws;
        }
    }
    for (int i = gid; i < 2 * 256; i += stride) {
        int l = i >> 8; int j = i & 255;
        const float* bf = l ? bf1 : bf0;
        const float* bs = l ? bs1 : bs0;
        d_bias2[l][j] = (j < 64) ? bf[j] : ((j < 128) ? bs[j - 64] : 0.f);
    }
}

// ---------------- CSR build (int atomics only) ----------------
__global__ void hist_kernel() {
    int e = blockIdx.x * blockDim.x + threadIdx.x;
    if (e < E_EDGES) atomicAdd(&d_deg[d_dst[e]], 1);
}

// single-block exclusive scan over 50k degrees
__global__ void scan_kernel() {
    const int T = 1024;
    const int per = (N_NODES + T - 1) / T;  // 49
    __shared__ int sh[T];
    int t = threadIdx.x;
    int base = t * per;
    int s = 0;
    for (int i = 0; i < per; i++) {
        int idx = base + i;
        if (idx < N_NODES) s += d_deg[idx];
    }
    sh[t] = s;
    __syncthreads();
    for (int off = 1; off < T; off <<= 1) {
        int v = (t >= off) ? sh[t - off] : 0;
        __syncthreads();
        sh[t] += v;
        __syncthreads();
    }
    int run = sh[t] - s;  // exclusive prefix
    for (int i = 0; i < per; i++) {
        int idx = base + i;
        if (idx < N_NODES) { d_rowptr[idx] = run; run += d_deg[idx]; }
    }
    if (t == T - 1) d_rowptr[N_NODES] = run;
}

__global__ void scatter_kernel(const float* __restrict__ ea) {
    int e = blockIdx.x * blockDim.x + threadIdx.x;
    if (e >= E_EDGES) return;
    int dn = d_dst[e];
    int pos = d_rowptr[dn] + atomicAdd(&d_fill[dn], 1);
    pos = min(max(pos, 0), E_EDGES - 1);
    d_esrc[pos] = d_src[e];
    const float4* A = (const float4*)&ea[(size_t)e * 16];
    float4* B = (float4*)&d_ea_s[(size_t)pos * 16];
    B[0] = A[0]; B[1] = A[1]; B[2] = A[2]; B[3] = A[3];
}

// ---------------- node GEMM: P[n][256] = x[n][64] @ Wnode + bias ----------------
__global__ __launch_bounds__(256) void node_gemm_kernel(const float* __restrict__ x_in, int layer) {
    __shared__ __align__(16) float sX[64 * 68];  // [k][n], stride 68 floats
    __shared__ float sB[256];
    int t = threadIdx.x;
    int n0 = blockIdx.x * 64;
    const float* __restrict__ x = (layer == 0) ? x_in : d_x1;
    const float* __restrict__ Wn = d_Wnode[layer];

    sB[t] = d_bias2[layer][t];
    {
        int n = t >> 2, q = t & 3;
        int node = n0 + n;
        #pragma unroll
        for (int i = 0; i < 4; i++) {
            int k = q * 16 + i * 4;
            float4 v = make_float4(0.f, 0.f, 0.f, 0.f);
            if (node < N_NODES) v = *(const float4*)&x[(size_t)node * 64 + k];
            sX[(k + 0) * 68 + n] = v.x;
            sX[(k + 1) * 68 + n] = v.y;
            sX[(k + 2) * 68 + n] = v.z;
            sX[(k + 3) * 68 + n] = v.w;
        }
    }
    __syncthreads();

    int tx = t & 31, ty = t >> 5;
    float acc[8][8];
    #pragma unroll
    for (int e = 0; e < 8; e++)
        #pragma unroll
        for (int j = 0; j < 8; j++) acc[e][j] = 0.f;

    #pragma unroll 8
    for (int k = 0; k < 64; k++) {
        float4 w0 = *(const float4*)&Wn[k * 256 + tx * 8];
        float4 w1 = *(const float4*)&Wn[k * 256 + tx * 8 + 4];
        float4 z0 = *(const float4*)&sX[k * 68 + ty * 8];
        float4 z1 = *(const float4*)&sX[k * 68 + ty * 8 + 4];
        float ww[8] = {w0.x, w0.y, w0.z, w0.w, w1.x, w1.y, w1.z, w1.w};
        float zz[8] = {z0.x, z0.y, z0.z, z0.w, z1.x, z1.y, z1.z, z1.w};
        #pragma unroll
        for (int e = 0; e < 8; e++)
            #pragma unroll
            for (int j = 0; j < 8; j++) acc[e][j] += zz[e] * ww[j];
    }

    float b[8];
    #pragma unroll
    for (int j = 0; j < 8; j++) b[j] = sB[tx * 8 + j];
    #pragma unroll
    for (int e = 0; e < 8; e++) {
        int node = n0 + ty * 8 + e;
        if (node < N_NODES) {
            float4 o0 = make_float4(acc[e][0] + b[0], acc[e][1] + b[1], acc[e][2] + b[2], acc[e][3] + b[3]);
            float4 o1 = make_float4(acc[e][4] + b[4], acc[e][5] + b[5], acc[e][6] + b[6], acc[e][7] + b[7]);
            *(float4*)&d_P[(size_t)node * 256 + tx * 8]     = o0;
            *(float4*)&d_P[(size_t)node * 256 + tx * 8 + 4] = o1;
        }
    }
}

// ---------------- CSR consumer: one warp per dst row, lane = 2 channels ----------------
// y[row] = xbase[row] + sum_e sigmoid(fd+fs+qf) * softplus(sd+ss+qs). No atomics.
// Software-pipelined: gathers for edge e+1 issued before the math of edge e.
__global__ __launch_bounds__(256) void csr_kernel(const float* __restrict__ x_in, int layer) {
    const float* __restrict__ Wq = d_Wq[layer];
    const float* __restrict__ xb = layer ? d_x1 : x_in;
    float* __restrict__ y = layer ? d_y1 : d_y0;
    int gwarp = (blockIdx.x * blockDim.x + threadIdx.x) >> 5;
    int nwarps = (gridDim.x * blockDim.x) >> 5;
    int lane = threadIdx.x & 31;
    int c0 = lane * 2;

    // per-lane register-resident edge-attr weights (loop invariant)
    float wf0[16], wf1[16], ws0[16], ws1[16];
    #pragma unroll
    for (int k = 0; k < 16; k++) {
        float2 wf = *(const float2*)&Wq[k * 128 + c0];
        float2 ws = *(const float2*)&Wq[k * 128 + 64 + c0];
        wf0[k] = wf.x; wf1[k] = wf.y; ws0[k] = ws.x; ws1[k] = ws.y;
    }

    for (int row = gwarp; row < N_NODES; row += nwarps) {
        int e0 = d_rowptr[row];
        int e1 = d_rowptr[row + 1];
        const float* Pr = d_P + (size_t)row * 256;
        float2 fd = *(const float2*)&Pr[c0];
        float2 sd = *(const float2*)&Pr[64 + c0];
        float acc0 = 0.f, acc1 = 0.f;

        if (e0 < e1) {
            // prologue: issue loads for first edge
            int src = d_esrc[e0];
            const float* Ps = d_P + (size_t)src * 256;
            float2 fs = *(const float2*)&Ps[128 + c0];
            float2 ss = *(const float2*)&Ps[192 + c0];
            const float4* A = (const float4*)&d_ea_s[(size_t)e0 * 16];
            float4 a0 = A[0], a1 = A[1], a2 = A[2], a3 = A[3];

            for (int e = e0; e < e1; e++) {
                float2 cfs = fs, css = ss;
                float4 ca0 = a0, ca1 = a1, ca2 = a2, ca3 = a3;
                if (e + 1 < e1) {
                    int nsrc = d_esrc[e + 1];
                    const float* Pn = d_P + (size_t)nsrc * 256;
                    fs = *(const float2*)&Pn[128 + c0];
                    ss = *(const float2*)&Pn[192 + c0];
                    const float4* An = (const float4*)&d_ea_s[(size_t)(e + 1) * 16];
                    a0 = An[0]; a1 = An[1]; a2 = An[2]; a3 = An[3];
                }
                float ea[16] = {ca0.x, ca0.y, ca0.z, ca0.w, ca1.x, ca1.y, ca1.z, ca1.w,
                                ca2.x, ca2.y, ca2.z, ca2.w, ca3.x, ca3.y, ca3.z, ca3.w};
                float qf0 = 0.f, qf1 = 0.f, qs0 = 0.f, qs1 = 0.f;
                #pragma unroll
                for (int k = 0; k < 16; k++) {
                    qf0 += ea[k] * wf0[k];
                    qf1 += ea[k] * wf1[k];
                    qs0 += ea[k] * ws0[k];
                    qs1 += ea[k] * ws1[k];
                }
                float f0 = fd.x + cfs.x + qf0;
                float f1 = fd.y + cfs.y + qf1;
                float s0 = sd.x + css.x + qs0;
                float s1 = sd.y + css.y + qs1;
                acc0 += sigmoid_f(f0) * softplus_f(s0);
                acc1 += sigmoid_f(f1) * softplus_f(s1);
            }
        }
        float2 xv = *(const float2*)&xb[(size_t)row * 64 + c0];
        float2 o = make_float2(xv.x + acc0, xv.y + acc1);
        *(float2*)&y[(size_t)row * 64 + c0] = o;
    }
}

// ---------------- BN stats: per-block partials, NO atomics ----------------
__global__ __launch_bounds__(256) void stats_kernel(int layer) {
    __shared__ double ssum[256], ssq[256];
    const float* __restrict__ y = layer ? d_y1 : d_y0;
    int t = threadIdx.x;
    int c = t & 63, sub = t >> 6;
    double s = 0.0, q = 0.0;
    for (int r = blockIdx.x * 4 + sub; r < N_NODES; r += NB_STATS * 4) {
        double v = (double)y[(size_t)r * 64 + c];
        s += v; q += v * v;
    }
    ssum[t] = s; ssq[t] = q;
    __syncthreads();
    if (t < 128) { ssum[t] += ssum[t + 128]; ssq[t] += ssq[t + 128]; }
    __syncthreads();
    if (t < 64) {
        d_psum[blockIdx.x * 64 + c] = ssum[t] + ssum[t + 64];
        d_psq[blockIdx.x * 64 + c]  = ssq[t] + ssq[t + 64];
    }
}

__global__ void finalize_stats_kernel(int layer, const float* __restrict__ gamma,
                                      const float* __restrict__ beta) {
    int c = threadIdx.x;
    if (c < 64) {
        double s = 0.0, q = 0.0;
        for (int b = 0; b < NB_STATS; b++) {
            s += d_psum[b * 64 + c];
            q += d_psq[b * 64 + c];
        }
        double m = s / (double)N_NODES;
        double v = q / (double)N_NODES - m * m;
        double sc = (double)gamma[c] * rsqrt(v + 1e-5);
        d_scale[layer][c] = (float)sc;
        d_shift[layer][c] = (float)((double)beta[c] - m * sc);
    }
}

// apply BN(layer0): x1 = norm(y0)
__global__ void apply_kernel() {
    int idx = blockIdx.x * blockDim.x + threadIdx.x;   // over N_NODES*16 float4s
    if (idx >= N_NODES * 16) return;
    int c4 = idx & 15;
    float4 v  = ((const float4*)d_y0)[idx];
    float4 sc = ((const float4*)d_scale[0])[c4];
    float4 sh = ((const float4*)d_shift[0])[c4];
    float4 o = make_float4(v.x * sc.x + sh.x, v.y * sc.y + sh.y,
                           v.z * sc.z + sh.z, v.w * sc.w + sh.w);
    ((float4*)d_x1)[idx] = o;
}

// ---------------- graph boundaries via binary search (batch sorted, no atomics) ----------------
__global__ void bounds_kernel(const void* __restrict__ batch_raw) {
    int g = threadIdx.x;
    if (g > 64) return;
    const int b64 = d_b64;
    const long long* bL = (const long long*)batch_raw;
    const int*       bI = (const int*)batch_raw;
    int lo = 0, hi = N_NODES;
    while (lo < hi) {
        int mid = (lo + hi) >> 1;
        long long bv = b64 ? bL[mid] : (long long)bI[mid];
        if (bv < (long long)g) lo = mid + 1; else hi = mid;
    }
    d_bound[g] = lo;   // first row with batch >= g
}

// BN(layer1) fused with global-mean-pool: one block per graph, writes out directly
__global__ __launch_bounds__(256) void pool_kernel(float* __restrict__ out) {
    __shared__ float sred[256];
    int g = blockIdx.x;
    int t = threadIdx.x;
    int c = t & 63, sub = t >> 6;
    int r0 = d_bound[g], r1 = d_bound[g + 1];
    float sc = d_scale[1][c], sh = d_shift[1][c];
    float acc = 0.f;
    for (int r = r0 + sub; r < r1; r += 4)
        acc += d_y1[(size_t)r * 64 + c] * sc + sh;
    sred[t] = acc;
    __syncthreads();
    if (t < 128) sred[t] += sred[t + 128];
    __syncthreads();
    if (t < 64) {
        float total = sred[t] + sred[t + 64];
        float cnt = (float)(r1 - r0);
        out[g * 64 + c] = total / fmaxf(cnt, 1.f);
    }
}

// ---------------- launch ----------------
extern "C" void kernel_launch(void* const* d_in, const int* in_sizes, int n_in,
                              void* d_out, int out_size) {
    const float* x     = (const float*)d_in[0];
    const void*  ei    = d_in[1];
    const float* ea    = (const float*)d_in[2];
    const void*  batch = d_in[3];
    const float *Wf0 = (const float*)d_in[4],  *bf0 = (const float*)d_in[5];
    const float *Ws0 = (const float*)d_in[6],  *bs0 = (const float*)d_in[7];
    const float *g0  = (const float*)d_in[8],  *be0 = (const float*)d_in[9];
    const float *Wf1 = (const float*)d_in[10], *bf1 = (const float*)d_in[11];
    const float *Ws1 = (const float*)d_in[12], *bs1 = (const float*)d_in[13];
    const float *g1  = (const float*)d_in[14], *be1 = (const float*)d_in[15];
    float* out = (float*)d_out;

    const int nodeBlocks  = (N_NODES + 63) / 64;          // 782
    const int edgeGrid    = (E_EDGES + 255) / 256;        // 3125
    const int csrBlocks   = 782;                          // 6256 warps, ~8 rows each
    const int applyBlocks = (N_NODES * 16 + 255) / 256;

    detect_kernel<<<1, 32>>>((const int*)ei, (const int*)batch);
    prep_kernel<<<512, 256>>>(ei, Wf0, Ws0, bf0, bs0, Wf1, Ws1, bf1, bs1);
    hist_kernel<<<edgeGrid, 256>>>();
    scan_kernel<<<1, 1024>>>();
    scatter_kernel<<<edgeGrid, 256>>>(ea);
    bounds_kernel<<<1, 128>>>(batch);

    // layer 0
    node_gemm_kernel<<<nodeBlocks, 256>>>(x, 0);
    csr_kernel<<<csrBlocks, 256>>>(x, 0);
    stats_kernel<<<NB_STATS, 256>>>(0);
    finalize_stats_kernel<<<1, 64>>>(0, g0, be0);
    apply_kernel<<<applyBlocks, 256>>>();

    // layer 1
    node_gemm_kernel<<<nodeBlocks, 256>>>(x, 1);
    csr_kernel<<<csrBlocks, 256>>>(x, 1);
    stats_kernel<<<NB_STATS, 256>>>(1);
    finalize_stats_kernel<<<1, 64>>>(1, g1, be1);

    // pool + output (writes d_out directly)
    pool_kernel<<<64, 256>>>(out);
}

// round 6
// speedup vs baseline: 1.0949x; 1.0949x over previous
#include <cuda_runtime.h>
#include <cuda_bf16.h>
#include <cstdint>

#define N_NODES 50000
#define E_EDGES 800000
#define NB_STATS 240
#define NB_SCAN 196   // ceil(50000/256)

// ---------------- device scratch (static, no allocs) ----------------
__device__ __align__(16) float  d_P[(size_t)N_NODES * 256];   // packed: see layout below
__device__ __align__(16) float  d_y0[(size_t)N_NODES * 64];
__device__ __align__(16) float  d_y1[(size_t)N_NODES * 64];
__device__ int    d_src[E_EDGES];
__device__ int    d_dst[E_EDGES];
__device__ int    d_deg[N_NODES];
__device__ int    d_fill[N_NODES];
__device__ int    d_rowptr[N_NODES + 1];
__device__ int    d_bsum[NB_SCAN];
__device__ int    d_boff[NB_SCAN];
__device__ int    d_esrc[E_EDGES];
__device__ __align__(16) float  d_ea_s[(size_t)E_EDGES * 16]; // edge_attr permuted to CSR order
__device__ __align__(16) float  d_Wnode[2][64 * 256];         // packed-column node weights
__device__ __align__(16) float  d_WqT[2][128 * 16];           // edge-attr weights, [chan][k]
__device__ float  d_bias2[2][256];
__device__ float  d_psum[NB_STATS * 64];                      // per-block BN partials (fp32)
__device__ float  d_psq[NB_STATS * 64];
__device__ __align__(16) float  d_scale[2][64];
__device__ __align__(16) float  d_shift[2][64];
__device__ int    d_bound[65];                                // graph row boundaries
__device__ int    d_ei64;
__device__ int    d_b64;

// Packed P layout per node (256 floats):
//   dst region [0,128):   for channel c: pos = (c>>1)*4 + (c&1), sd at pos+2
//   src region [128,256): same mapping + 128  (fs / ss)
__device__ __forceinline__ int idx_fd(int c) { return ((c >> 1) << 2) + (c & 1); }

__device__ __forceinline__ float sigmoid_f(float x) {
    return __fdividef(1.f, 1.f + __expf(-x));
}
__device__ __forceinline__ float softplus_f(float x) {
    return (x > 20.f) ? x : __logf(1.f + __expf(x));
}
__device__ __forceinline__ uint64_t fma2(uint64_t a, uint64_t b, uint64_t c) {
    uint64_t d;
    asm("fma.rn.f32x2 %0, %1, %2, %3;" : "=l"(d) : "l"(a), "l"(b), "l"(c));
    return d;
}
__device__ __forceinline__ float2 unpack2(uint64_t v) {
    float2 r;
    asm("mov.b64 {%0, %1}, %2;" : "=f"(r.x), "=f"(r.y) : "l"(v));
    return r;
}

// ---------------- zero counters + dtype detection ----------------
__global__ void zero_detect_kernel(const int* __restrict__ ei32, const int* __restrict__ b32) {
    int stride = gridDim.x * blockDim.x;
    for (int i = blockIdx.x * blockDim.x + threadIdx.x; i < N_NODES; i += stride) {
        d_deg[i] = 0; d_fill[i] = 0;
    }
    if (blockIdx.x == 0 && threadIdx.x == 0) {
        int o = 0;
        #pragma unroll
        for (int i = 1; i < 64; i += 2) o |= ei32[i];     // high halves if int64
        d_ei64 = (o == 0) ? 1 : 0;
        d_b64 = (b32[N_NODES - 1] == 0) ? 1 : 0;
    }
}

// ---------------- prep: decode+clamp indices (+hist), pack weights ----------------
__global__ void prep_kernel(const void* __restrict__ ei_raw,
                            const float* __restrict__ Wf0, const float* __restrict__ Ws0,
                            const float* __restrict__ bf0, const float* __restrict__ bs0,
                            const float* __restrict__ Wf1, const float* __restrict__ Ws1,
                            const float* __restrict__ bf1, const float* __restrict__ bs1) {
    int stride = gridDim.x * blockDim.x;
    int gid = blockIdx.x * blockDim.x + threadIdx.x;
    const int ei64 = d_ei64;
    const long long* eL = (const long long*)ei_raw;
    const int*       eI = (const int*)ei_raw;
    for (int i = gid; i < E_EDGES; i += stride) {
        int s, d;
        if (ei64) { s = (int)eL[i]; d = (int)eL[E_EDGES + i]; }
        else      { s = eI[i];      d = eI[E_EDGES + i]; }
        s = min(max(s, 0), N_NODES - 1);
        d = min(max(d, 0), N_NODES - 1);
        d_src[i] = s;
        d_dst[i] = d;
        atomicAdd(&d_deg[d], 1);
    }
    for (int i = gid; i < 2 * 64 * 144; i += stride) {
        int l = i / 9216; int r = i % 9216; int j = r / 144; int k = r % 144;
        const float* Wf = l ? Wf1 : Wf0;
        const float* Ws = l ? Ws1 : Ws0;
        float wf = Wf[j * 144 + k], ws = Ws[j * 144 + k];
        int pf = idx_fd(j);
        if (k < 64) {
            d_Wnode[l][k * 256 + pf]     = wf;      // fd
            d_Wnode[l][k * 256 + pf + 2] = ws;      // sd
        } else if (k < 128) {
            int kk = k - 64;
            d_Wnode[l][kk * 256 + 128 + pf]     = wf;  // fs
            d_Wnode[l][kk * 256 + 128 + pf + 2] = ws;  // ss
        } else {
            int kk = k - 128;
            d_WqT[l][j * 16 + kk]        = wf;
            d_WqT[l][(64 + j) * 16 + kk] = ws;
        }
    }
    for (int i = gid; i < 2 * 64; i += stride) {
        int l = i >> 6; int j = i & 63;
        const float* bf = l ? bf1 : bf0;
        const float* bs = l ? bs1 : bs0;
        int pf = idx_fd(j);
        d_bias2[l][pf]           = bf[j];
        d_bias2[l][pf + 2]       = bs[j];
        d_bias2[l][128 + pf]     = 0.f;
        d_bias2[l][128 + pf + 2] = 0.f;
    }
}

// ---------------- CSR scan: 3 small kernels ----------------
__global__ void scan1_kernel() {
    __shared__ int sh[256];
    int t = threadIdx.x;
    int i = blockIdx.x * 256 + t;
    sh[t] = (i < N_NODES) ? d_deg[i] : 0;
    __syncthreads();
    for (int off = 128; off > 0; off >>= 1) {
        if (t < off) sh[t] += sh[t + off];
        __syncthreads();
    }
    if (t == 0) d_bsum[blockIdx.x] = sh[0];
}

__global__ void scan2_kernel() {
    __shared__ int sh[256];
    int t = threadIdx.x;
    int v = (t < NB_SCAN) ? d_bsum[t] : 0;
    sh[t] = v;
    __syncthreads();
    for (int off = 1; off < 256; off <<= 1) {
        int u = (t >= off) ? sh[t - off] : 0;
        __syncthreads();
        sh[t] += u;
        __syncthreads();
    }
    if (t < NB_SCAN) d_boff[t] = sh[t] - v;
    if (t == 255) d_rowptr[N_NODES] = sh[255];
}

__global__ void scan3_kernel() {
    __shared__ int sh[256];
    int t = threadIdx.x;
    int i = blockIdx.x * 256 + t;
    int v = (i < N_NODES) ? d_deg[i] : 0;
    sh[t] = v;
    __syncthreads();
    for (int off = 1; off < 256; off <<= 1) {
        int u = (t >= off) ? sh[t - off] : 0;
        __syncthreads();
        sh[t] += u;
        __syncthreads();
    }
    if (i < N_NODES) d_rowptr[i] = sh[t] - v + d_boff[blockIdx.x];
}

__global__ void scatter_kernel(const float* __restrict__ ea) {
    int e = blockIdx.x * blockDim.x + threadIdx.x;
    if (e >= E_EDGES) return;
    int dn = d_dst[e];
    int pos = d_rowptr[dn] + atomicAdd(&d_fill[dn], 1);
    pos = min(max(pos, 0), E_EDGES - 1);
    d_esrc[pos] = d_src[e];
    const float4* A = (const float4*)&ea[(size_t)e * 16];
    float4* B = (float4*)&d_ea_s[(size_t)pos * 16];
    B[0] = A[0]; B[1] = A[1]; B[2] = A[2]; B[3] = A[3];
}

// ---------------- node GEMM: P[n][256] = in[n][64] @ Wnode + bias ----------------
// layer 1 input = BN0(y0), applied inline.
__global__ __launch_bounds__(256) void node_gemm_kernel(const float* __restrict__ x_in, int layer) {
    __shared__ __align__(16) float sX[64 * 68];  // [k][n], stride 68 floats
    __shared__ float sB[256];
    __shared__ float sSc[64], sSh[64];
    int t = threadIdx.x;
    int n0 = blockIdx.x * 64;
    const float* __restrict__ src = layer ? d_y0 : x_in;
    const float* __restrict__ Wn = d_Wnode[layer];

    sB[t] = d_bias2[layer][t];
    if (t < 64) {
        sSc[t] = layer ? d_scale[0][t] : 1.f;
        sSh[t] = layer ? d_shift[0][t] : 0.f;
    }
    __syncthreads();
    {
        int n = t >> 2, q = t & 3;
        int node = n0 + n;
        #pragma unroll
        for (int i = 0; i < 4; i++) {
            int k = q * 16 + i * 4;
            float4 v = make_float4(0.f, 0.f, 0.f, 0.f);
            if (node < N_NODES) v = *(const float4*)&src[(size_t)node * 64 + k];
            sX[(k + 0) * 68 + n] = v.x * sSc[k + 0] + sSh[k + 0];
            sX[(k + 1) * 68 + n] = v.y * sSc[k + 1] + sSh[k + 1];
            sX[(k + 2) * 68 + n] = v.z * sSc[k + 2] + sSh[k + 2];
            sX[(k + 3) * 68 + n] = v.w * sSc[k + 3] + sSh[k + 3];
        }
    }
    __syncthreads();

    int tx = t & 31, ty = t >> 5;
    float acc[8][8];
    #pragma unroll
    for (int e = 0; e < 8; e++)
        #pragma unroll
        for (int j = 0; j < 8; j++) acc[e][j] = 0.f;

    #pragma unroll 8
    for (int k = 0; k < 64; k++) {
        float4 w0 = *(const float4*)&Wn[k * 256 + tx * 8];
        float4 w1 = *(const float4*)&Wn[k * 256 + tx * 8 + 4];
        float4 z0 = *(const float4*)&sX[k * 68 + ty * 8];
        float4 z1 = *(const float4*)&sX[k * 68 + ty * 8 + 4];
        float ww[8] = {w0.x, w0.y, w0.z, w0.w, w1.x, w1.y, w1.z, w1.w};
        float zz[8] = {z0.x, z0.y, z0.z, z0.w, z1.x, z1.y, z1.z, z1.w};
        #pragma unroll
        for (int e = 0; e < 8; e++)
            #pragma unroll
            for (int j = 0; j < 8; j++) acc[e][j] += zz[e] * ww[j];
    }

    float b[8];
    #pragma unroll
    for (int j = 0; j < 8; j++) b[j] = sB[tx * 8 + j];
    #pragma unroll
    for (int e = 0; e < 8; e++) {
        int node = n0 + ty * 8 + e;
        if (node < N_NODES) {
            float4 o0 = make_float4(acc[e][0] + b[0], acc[e][1] + b[1], acc[e][2] + b[2], acc[e][3] + b[3]);
            float4 o1 = make_float4(acc[e][4] + b[4], acc[e][5] + b[5], acc[e][6] + b[6], acc[e][7] + b[7]);
            *(float4*)&d_P[(size_t)node * 256 + tx * 8]     = o0;
            *(float4*)&d_P[(size_t)node * 256 + tx * 8 + 4] = o1;
        }
    }
}

// ---------------- CSR consumer: one warp per dst row, lane = 2 channels ----------------
// Packed-P gathers (1x LDG.128/side), f32x2 edge-attr dot, software-pipelined.
__global__ __launch_bounds__(256) void csr_kernel(const float* __restrict__ x_in, int layer) {
    const float* __restrict__ WqT = d_WqT[layer];
    float* __restrict__ y = layer ? d_y1 : d_y0;
    int gwarp = (blockIdx.x * blockDim.x + threadIdx.x) >> 5;
    int nwarps = (gridDim.x * blockDim.x) >> 5;
    int lane = threadIdx.x & 31;
    int c0 = lane * 2;

    // per-lane weights: 4 channel-rows x 16 k, as f32x2 pairs over k
    uint64_t wq0[8], wq1[8], wq2[8], wq3[8];
    {
        const uint64_t* W0 = (const uint64_t*)&WqT[c0 * 16];
        const uint64_t* W1 = (const uint64_t*)&WqT[(c0 + 1) * 16];
        const uint64_t* W2 = (const uint64_t*)&WqT[(64 + c0) * 16];
        const uint64_t* W3 = (const uint64_t*)&WqT[(65 + c0) * 16];
        #pragma unroll
        for (int k = 0; k < 8; k++) { wq0[k] = W0[k]; wq1[k] = W1[k]; wq2[k] = W2[k]; wq3[k] = W3[k]; }
    }
    float2 rs = make_float2(1.f, 1.f), rh = make_float2(0.f, 0.f);
    if (layer) {
        rs = *(const float2*)&d_scale[0][c0];
        rh = *(const float2*)&d_shift[0][c0];
    }

    for (int row = gwarp; row < N_NODES; row += nwarps) {
        int e0 = d_rowptr[row], e1 = d_rowptr[row + 1];
        float4 dp = *(const float4*)&d_P[(size_t)row * 256 + lane * 4];  // {fd0,fd1,sd0,sd1}
        float acc0 = 0.f, acc1 = 0.f;

        if (e0 < e1) {
            int src = d_esrc[e0];
            float4 sp = *(const float4*)&d_P[(size_t)src * 256 + 128 + lane * 4];
            const ulonglong2* Au = (const ulonglong2*)&d_ea_s[(size_t)e0 * 16];
            ulonglong2 u0 = Au[0], u1 = Au[1], u2 = Au[2], u3 = Au[3];

            for (int e = e0; e < e1; e++) {
                float4 csp = sp;
                uint64_t ep[8] = {u0.x, u0.y, u1.x, u1.y, u2.x, u2.y, u3.x, u3.y};
                if (e + 1 < e1) {
                    int ns = d_esrc[e + 1];
                    sp = *(const float4*)&d_P[(size_t)ns * 256 + 128 + lane * 4];
                    const ulonglong2* An = (const ulonglong2*)&d_ea_s[(size_t)(e + 1) * 16];
                    u0 = An[0]; u1 = An[1]; u2 = An[2]; u3 = An[3];
                }
                uint64_t qf0 = 0, qf1 = 0, qs0 = 0, qs1 = 0;
                #pragma unroll
                for (int k = 0; k < 8; k++) {
                    qf0 = fma2(wq0[k], ep[k], qf0);
                    qf1 = fma2(wq1[k], ep[k], qf1);
                    qs0 = fma2(wq2[k], ep[k], qs0);
                    qs1 = fma2(wq3[k], ep[k], qs1);
                }
                float2 h0 = unpack2(qf0), h1 = unpack2(qf1), h2 = unpack2(qs0), h3 = unpack2(qs1);
                float f0 = dp.x + csp.x + (h0.x + h0.y);
                float f1 = dp.y + csp.y + (h1.x + h1.y);
                float s0 = dp.z + csp.z + (h2.x + h2.y);
                float s1 = dp.w + csp.w + (h3.x + h3.y);
                acc0 += sigmoid_f(f0) * softplus_f(s0);
                acc1 += sigmoid_f(f1) * softplus_f(s1);
            }
        }
        float2 xv;
        if (layer) {
            float2 tv = *(const float2*)&d_y0[(size_t)row * 64 + c0];
            xv = make_float2(tv.x * rs.x + rh.x, tv.y * rs.y + rh.y);
        } else {
            xv = *(const float2*)&x_in[(size_t)row * 64 + c0];
        }
        *(float2*)&y[(size_t)row * 64 + c0] = make_float2(xv.x + acc0, xv.y + acc1);
    }
}

// ---------------- BN stats: fp32 per-block partials, no atomics, no fp64 hot loop ----------------
__global__ __launch_bounds__(256) void stats_kernel(int layer) {
    __shared__ float ssum[256], ssq[256];
    const float* __restrict__ y = layer ? d_y1 : d_y0;
    int t = threadIdx.x;
    int c = t & 63, sub = t >> 6;
    float s = 0.f, q = 0.f;
    for (int r = blockIdx.x * 4 + sub; r < N_NODES; r += NB_STATS * 4) {
        float v = y[(size_t)r * 64 + c];
        s += v;
        q = fmaf(v, v, q);
    }
    ssum[t] = s; ssq[t] = q;
    __syncthreads();
    if (t < 128) { ssum[t] += ssum[t + 128]; ssq[t] += ssq[t + 128]; }
    __syncthreads();
    if (t < 64) {
        d_psum[blockIdx.x * 64 + c] = ssum[t] + ssum[t + 64];
        d_psq[blockIdx.x * 64 + c]  = ssq[t] + ssq[t + 64];
    }
}

__global__ void finalize_stats_kernel(int layer, const float* __restrict__ gamma,
                                      const float* __restrict__ beta) {
    int c = threadIdx.x;
    if (c < 64) {
        double s = 0.0, q = 0.0;
        for (int b = 0; b < NB_STATS; b++) {
            s += (double)d_psum[b * 64 + c];
            q += (double)d_psq[b * 64 + c];
        }
        double m = s / (double)N_NODES;
        double v = q / (double)N_NODES - m * m;
        double sc = (double)gamma[c] * rsqrt(v + 1e-5);
        d_scale[layer][c] = (float)sc;
        d_shift[layer][c] = (float)((double)beta[c] - m * sc);
    }
}

// ---------------- graph boundaries via binary search ----------------
__global__ void bounds_kernel(const void* __restrict__ batch_raw) {
    int g = threadIdx.x;
    if (g > 64) return;
    const int b64 = d_b64;
    const long long* bL = (const long long*)batch_raw;
    const int*       bI = (const int*)batch_raw;
    int lo = 0, hi = N_NODES;
    while (lo < hi) {
        int mid = (lo + hi) >> 1;
        long long bv = b64 ? bL[mid] : (long long)bI[mid];
        if (bv < (long long)g) lo = mid + 1; else hi = mid;
    }
    d_bound[g] = lo;
}

// BN(layer1) fused with global-mean-pool: one block per graph
__global__ __launch_bounds__(256) void pool_kernel(float* __restrict__ out) {
    __shared__ float sred[256];
    int g = blockIdx.x;
    int t = threadIdx.x;
    int c = t & 63, sub = t >> 6;
    int r0 = d_bound[g], r1 = d_bound[g + 1];
    float sc = d_scale[1][c], sh = d_shift[1][c];
    float acc = 0.f;
    for (int r = r0 + sub; r < r1; r += 4)
        acc += d_y1[(size_t)r * 64 + c] * sc + sh;
    sred[t] = acc;
    __syncthreads();
    if (t < 128) sred[t] += sred[t + 128];
    __syncthreads();
    if (t < 64) {
        float total = sred[t] + sred[t + 64];
        float cnt = (float)(r1 - r0);
        out[g * 64 + c] = total / fmaxf(cnt, 1.f);
    }
}

// ---------------- launch ----------------
extern "C" void kernel_launch(void* const* d_in, const int* in_sizes, int n_in,
                              void* d_out, int out_size) {
    const float* x     = (const float*)d_in[0];
    const void*  ei    = d_in[1];
    const float* ea    = (const float*)d_in[2];
    const void*  batch = d_in[3];
    const float *Wf0 = (const float*)d_in[4],  *bf0 = (const float*)d_in[5];
    const float *Ws0 = (const float*)d_in[6],  *bs0 = (const float*)d_in[7];
    const float *g0  = (const float*)d_in[8],  *be0 = (const float*)d_in[9];
    const float *Wf1 = (const float*)d_in[10], *bf1 = (const float*)d_in[11];
    const float *Ws1 = (const float*)d_in[12], *bs1 = (const float*)d_in[13];
    const float *g1  = (const float*)d_in[14], *be1 = (const float*)d_in[15];
    float* out = (float*)d_out;

    const int nodeBlocks = (N_NODES + 63) / 64;          // 782
    const int edgeGrid   = (E_EDGES + 255) / 256;        // 3125
    const int csrBlocks  = 782;                          // 6256 warps, ~8 rows each

    zero_detect_kernel<<<NB_SCAN, 256>>>((const int*)ei, (const int*)batch);
    prep_kernel<<<512, 256>>>(ei, Wf0, Ws0, bf0, bs0, Wf1, Ws1, bf1, bs1);
    scan1_kernel<<<NB_SCAN, 256>>>();
    scan2_kernel<<<1, 256>>>();
    scan3_kernel<<<NB_SCAN, 256>>>();
    scatter_kernel<<<edgeGrid, 256>>>(ea);
    bounds_kernel<<<1, 128>>>(batch);

    // layer 0
    node_gemm_kernel<<<nodeBlocks, 256>>>(x, 0);
    csr_kernel<<<csrBlocks, 256>>>(x, 0);
    stats_kernel<<<NB_STATS, 256>>>(0);
    finalize_stats_kernel<<<1, 64>>>(0, g0, be0);

    // layer 1 (BN0 folded into node_gemm input + csr residual)
    node_gemm_kernel<<<nodeBlocks, 256>>>(x, 1);
    csr_kernel<<<csrBlocks, 256>>>(x, 1);
    stats_kernel<<<NB_STATS, 256>>>(1);
    finalize_stats_kernel<<<1, 64>>>(1, g1, be1);

    // pool + output
    pool_kernel<<<64, 256>>>(out);
}